// round 2
// baseline (speedup 1.0000x reference)
#include <cuda_runtime.h>
#include <math.h>

#define BB 8
#define TT 2048
#define DD 256
#define BT (BB*TT)

// ---------------- scratch (static device arrays; no cudaMalloc allowed) ----
__device__ float g_q[BT*DD];
__device__ float g_k[BT*DD];
__device__ float g_v1[BT*DD];   // LN'd v before gate
__device__ float g_v[BT*DD];    // gated v
__device__ float g_weff[DD*DD];
__device__ float g_bq[BB*DD];
__device__ float g_bk[BB*DD];
__device__ float g_bv[BB*DD];
__device__ float g_vpart[BB*16*DD];
__device__ float g_vmean[BB*DD];

// ---------------- small 256x256x256 matmul: C = A @ B -----------------------
__global__ void matmul256_kernel(const float* __restrict__ A,
                                 const float* __restrict__ Bm,
                                 float* __restrict__ C)
{
    __shared__ float As[16][16];
    __shared__ float Bs[16][17];
    int tx = threadIdx.x, ty = threadIdx.y;
    int row = blockIdx.y * 16 + ty;
    int col = blockIdx.x * 16 + tx;
    float acc = 0.f;
    for (int k0 = 0; k0 < DD; k0 += 16) {
        As[ty][tx] = A[row * DD + k0 + tx];
        Bs[ty][tx] = Bm[(k0 + ty) * DD + col];
        __syncthreads();
#pragma unroll
        for (int k = 0; k < 16; k++) acc += As[ty][k] * Bs[k][tx];
        __syncthreads();
    }
    C[row * DD + col] = acc;
}

// ---------------- per-batch effective bias ---------------------------------
// out[b][n] = bblk[n] + sum_d aux[b][d]*WB[d][n] (+ sum_d bin[d]*WA[d][n] if fold)
__global__ void bias_kernel(const float* __restrict__ aux,
                            const float* __restrict__ WB,
                            const float* __restrict__ bblk,
                            const float* __restrict__ bin,
                            const float* __restrict__ WA,
                            int fold,
                            float* __restrict__ outBD)
{
    int b = blockIdx.x, n = threadIdx.x;
    float acc = bblk[n];
    for (int d = 0; d < DD; d++) acc += aux[b * DD + d] * WB[d * DD + n];
    if (fold) {
        for (int d = 0; d < DD; d++) acc += bin[d] * WA[d * DD + n];
    }
    outBD[b * DD + n] = acc;
}

// ---------------- fused GEMM (16384x256 @ 256x256) + bias + PReLU + LN -----
#define GROWS 32
#define KC 32
__global__ __launch_bounds__(256) void gemm_ln_kernel(
    const float* __restrict__ X, const float* __restrict__ W,
    const float* __restrict__ biasBD, const float* __restrict__ aP,
    const float* __restrict__ gam, const float* __restrict__ beta,
    float* __restrict__ out)
{
    __shared__ float Xs[GROWS][KC];   // 4KB
    __shared__ float Ws[KC][DD];      // 32KB
    int tid = threadIdx.x;
    int ty = tid >> 5, tx = tid & 31;  // warp = 4 rows
    int row0 = blockIdx.x * GROWS;

    float acc[4][8];
#pragma unroll
    for (int i = 0; i < 4; i++)
#pragma unroll
        for (int j = 0; j < 8; j++) acc[i][j] = 0.f;

    for (int k0 = 0; k0 < DD; k0 += KC) {
        // load X tile: 32x32 floats = 256 float4, one per thread
        {
            int r = tid >> 3, c4 = tid & 7;
            ((float4*)&Xs[r][0])[c4] =
                ((const float4*)(X + (size_t)(row0 + r) * DD + k0))[c4];
        }
        // load W tile: 32x256 = 2048 float4, 8 per thread
#pragma unroll
        for (int it = 0; it < 8; it++) {
            int i = tid + it * 256;
            int r = i >> 6, c4 = i & 63;
            ((float4*)&Ws[r][0])[c4] =
                ((const float4*)(W + (size_t)(k0 + r) * DD))[c4];
        }
        __syncthreads();
#pragma unroll
        for (int kk = 0; kk < KC; kk++) {
            float xv[4], wv[8];
#pragma unroll
            for (int i = 0; i < 4; i++) xv[i] = Xs[4 * ty + i][kk];
#pragma unroll
            for (int j = 0; j < 8; j++) wv[j] = Ws[kk][tx + 32 * j];
#pragma unroll
            for (int i = 0; i < 4; i++)
#pragma unroll
                for (int j = 0; j < 8; j++) acc[i][j] += xv[i] * wv[j];
        }
        __syncthreads();
    }

    // epilogue: bias + PReLU + LayerNorm per row (warp owns 4 full rows)
    int b = row0 / TT;
    float a = aP[0];
    float gv[8], bv2[8], bias[8];
#pragma unroll
    for (int j = 0; j < 8; j++) {
        int col = tx + 32 * j;
        bias[j] = biasBD[b * DD + col];
        gv[j] = gam[col];
        bv2[j] = beta[col];
    }
#pragma unroll
    for (int i = 0; i < 4; i++) {
        float v[8];
        float sum = 0.f;
#pragma unroll
        for (int j = 0; j < 8; j++) {
            float t = acc[i][j] + bias[j];
            t = (t >= 0.f) ? t : a * t;   // PReLU
            v[j] = t;
            sum += t;
        }
#pragma unroll
        for (int o = 16; o > 0; o >>= 1) sum += __shfl_xor_sync(0xffffffffu, sum, o);
        float mean = sum * (1.f / DD);
        float sq = 0.f;
#pragma unroll
        for (int j = 0; j < 8; j++) { float d = v[j] - mean; sq += d * d; }
#pragma unroll
        for (int o = 16; o > 0; o >>= 1) sq += __shfl_xor_sync(0xffffffffu, sq, o);
        float rstd = rsqrtf(sq * (1.f / DD) + 1e-5f);
        int row = row0 + 4 * ty + i;
        float* orow = out + (size_t)row * DD;
#pragma unroll
        for (int j = 0; j < 8; j++)
            orow[tx + 32 * j] = (v[j] - mean) * rstd * gv[j] + bv2[j];
    }
}

// ---------------- gate: v = sigmoid(x@Ws+bs) * tanh(x@Wt+bt) ---------------
#define KCG 16
__global__ __launch_bounds__(256) void gate_kernel(
    const float* __restrict__ X, const float* __restrict__ Wsm,
    const float* __restrict__ Wtm, const float* __restrict__ bs,
    const float* __restrict__ bt, float* __restrict__ out)
{
    __shared__ float Xs[GROWS][KCG];   // 2KB
    __shared__ float Wss[KCG][DD];     // 16KB
    __shared__ float Wts[KCG][DD];     // 16KB
    int tid = threadIdx.x;
    int ty = tid >> 5, tx = tid & 31;
    int row0 = blockIdx.x * GROWS;

    float accs[4][8], acct[4][8];
#pragma unroll
    for (int i = 0; i < 4; i++)
#pragma unroll
        for (int j = 0; j < 8; j++) { accs[i][j] = 0.f; acct[i][j] = 0.f; }

    for (int k0 = 0; k0 < DD; k0 += KCG) {
        // X tile: 32x16 = 128 float4
        if (tid < 128) {
            int r = tid >> 2, c4 = tid & 3;
            ((float4*)&Xs[r][0])[c4] =
                ((const float4*)(X + (size_t)(row0 + r) * DD + k0))[c4];
        }
        // W tiles: 16x256 = 1024 float4 each, 4 per thread each
#pragma unroll
        for (int it = 0; it < 4; it++) {
            int i = tid + it * 256;
            int r = i >> 6, c4 = i & 63;
            ((float4*)&Wss[r][0])[c4] =
                ((const float4*)(Wsm + (size_t)(k0 + r) * DD))[c4];
            ((float4*)&Wts[r][0])[c4] =
                ((const float4*)(Wtm + (size_t)(k0 + r) * DD))[c4];
        }
        __syncthreads();
#pragma unroll
        for (int kk = 0; kk < KCG; kk++) {
            float xv[4], ws[8], wt[8];
#pragma unroll
            for (int i = 0; i < 4; i++) xv[i] = Xs[4 * ty + i][kk];
#pragma unroll
            for (int j = 0; j < 8; j++) {
                ws[j] = Wss[kk][tx + 32 * j];
                wt[j] = Wts[kk][tx + 32 * j];
            }
#pragma unroll
            for (int i = 0; i < 4; i++)
#pragma unroll
                for (int j = 0; j < 8; j++) {
                    accs[i][j] += xv[i] * ws[j];
                    acct[i][j] += xv[i] * wt[j];
                }
        }
        __syncthreads();
    }

#pragma unroll
    for (int i = 0; i < 4; i++) {
        int row = row0 + 4 * ty + i;
        float* orow = out + (size_t)row * DD;
#pragma unroll
        for (int j = 0; j < 8; j++) {
            int col = tx + 32 * j;
            float s = accs[i][j] + bs[col];
            float t = acct[i][j] + bt[col];
            float sig = 1.f / (1.f + __expf(-s));
            orow[col] = sig * tanhf(t);
        }
    }
}

// ---------------- v column means (for pad rows) -----------------------------
__global__ void vpart_kernel()
{
    int b = blockIdx.x, c = blockIdx.y, d = threadIdx.x;
    float s = 0.f;
    const float* base = g_v + ((size_t)(b * TT + c * 128)) * DD + d;
    for (int i = 0; i < 128; i++) s += base[(size_t)i * DD];
    g_vpart[(b * 16 + c) * DD + d] = s;
}

__global__ void vmean_kernel()
{
    int b = blockIdx.x, d = threadIdx.x;
    float s = 0.f;
    for (int c = 0; c < 16; c++) s += g_vpart[(b * 16 + c) * DD + d];
    g_vmean[b * DD + d] = s * (1.f / TT);
}

// ---------------- flash attention (fp32, causal, valid rows) ----------------
#define FBM 64
#define FBN 64
#define QSTR 257
#define PSTR 68

__global__ __launch_bounds__(256, 1) void flash_kernel(
    const int* __restrict__ lenp, float* __restrict__ out)
{
    extern __shared__ float sm[];
    float* Qs = sm;                        // 64 x 257
    float* Ks = Qs + FBM * QSTR;           // 64 x 257
    float* Vs = Ks + FBN * QSTR;           // 64 x 256
    float* Ps = Vs + FBN * DD;             // 64 x 68

    int b = blockIdx.y;
    int qt = gridDim.x - 1 - blockIdx.x;   // big tiles launch first
    int tid = threadIdx.x;
    int ty = tid >> 4, tx = tid & 15;
    int r0 = qt * FBM;

    const float SCALE = 1.f / 16.f;        // 1/sqrt(256)

    // load Q tile (pre-scaled)
    {
        const float* qbase = g_q + ((size_t)(b * TT + r0)) * DD;
#pragma unroll
        for (int it = 0; it < 16; it++) {
            int i = tid + it * 256;        // 4096 float4 total
            int r = i >> 6, c4 = i & 63;
            float4 v = ((const float4*)(qbase + (size_t)r * DD))[c4];
            float* dst = Qs + r * QSTR + c4 * 4;
            dst[0] = v.x * SCALE; dst[1] = v.y * SCALE;
            dst[2] = v.z * SCALE; dst[3] = v.w * SCALE;
        }
    }

    float m_i[4], l_i[4], acc[4][16];
#pragma unroll
    for (int i = 0; i < 4; i++) {
        m_i[i] = -1e30f; l_i[i] = 0.f;
#pragma unroll
        for (int j = 0; j < 16; j++) acc[i][j] = 0.f;
    }
    __syncthreads();

    for (int st = 0; st <= qt; ++st) {
        int s0 = st * FBN;
        // load K, V tiles
        {
            const float* kbase = g_k + ((size_t)(b * TT + s0)) * DD;
            const float* vbase = g_v + ((size_t)(b * TT + s0)) * DD;
#pragma unroll
            for (int it = 0; it < 16; it++) {
                int i = tid + it * 256;
                int r = i >> 6, c4 = i & 63;
                float4 kv = ((const float4*)(kbase + (size_t)r * DD))[c4];
                float* kd = Ks + r * QSTR + c4 * 4;
                kd[0] = kv.x; kd[1] = kv.y; kd[2] = kv.z; kd[3] = kv.w;
                ((float4*)(Vs + r * DD))[c4] =
                    ((const float4*)(vbase + (size_t)r * DD))[c4];
            }
        }
        __syncthreads();

        // S = Q @ K^T : rows 4ty+i, cols tx+16j
        float sacc[4][4];
#pragma unroll
        for (int i = 0; i < 4; i++)
#pragma unroll
            for (int j = 0; j < 4; j++) sacc[i][j] = 0.f;

        const float* qrow0 = Qs + (4 * ty) * QSTR;
        const float* kcol0 = Ks + tx * QSTR;
#pragma unroll 4
        for (int k = 0; k < DD; k++) {
            float qv[4], kv[4];
#pragma unroll
            for (int i = 0; i < 4; i++) qv[i] = qrow0[i * QSTR + k];
#pragma unroll
            for (int j = 0; j < 4; j++) kv[j] = kcol0[j * 16 * QSTR + k];
#pragma unroll
            for (int i = 0; i < 4; i++)
#pragma unroll
                for (int j = 0; j < 4; j++) sacc[i][j] += qv[i] * kv[j];
        }

        // causal mask on diagonal tile
        if (st == qt) {
#pragma unroll
            for (int i = 0; i < 4; i++)
#pragma unroll
                for (int j = 0; j < 4; j++)
                    if (s0 + tx + 16 * j > r0 + 4 * ty + i) sacc[i][j] = -1e30f;
        }

        // online softmax
        float mnew[4], lad[4];
#pragma unroll
        for (int i = 0; i < 4; i++) {
            float mx = sacc[i][0];
#pragma unroll
            for (int j = 1; j < 4; j++) mx = fmaxf(mx, sacc[i][j]);
#pragma unroll
            for (int o = 1; o < 16; o <<= 1)
                mx = fmaxf(mx, __shfl_xor_sync(0xffffffffu, mx, o));
            mnew[i] = fmaxf(m_i[i], mx);
        }
#pragma unroll
        for (int i = 0; i < 4; i++) {
            float sum = 0.f;
            float* prow = Ps + (4 * ty + i) * PSTR;
#pragma unroll
            for (int j = 0; j < 4; j++) {
                float p = __expf(sacc[i][j] - mnew[i]);
                sum += p;
                prow[tx + 16 * j] = p;
            }
#pragma unroll
            for (int o = 1; o < 16; o <<= 1)
                sum += __shfl_xor_sync(0xffffffffu, sum, o);
            lad[i] = sum;
        }
#pragma unroll
        for (int i = 0; i < 4; i++) {
            float f = __expf(m_i[i] - mnew[i]);
            l_i[i] = l_i[i] * f + lad[i];
            m_i[i] = mnew[i];
#pragma unroll
            for (int j = 0; j < 16; j++) acc[i][j] *= f;
        }
        __syncthreads();

        // O += P @ V : rows 4ty+i, cols tx+16j
        const float* prow0 = Ps + (4 * ty) * PSTR;
#pragma unroll 2
        for (int kk = 0; kk < FBN; kk++) {
            float p[4];
#pragma unroll
            for (int i = 0; i < 4; i++) p[i] = prow0[i * PSTR + kk];
            const float* vr = Vs + kk * DD;
#pragma unroll
            for (int j = 0; j < 16; j++) {
                float vv = vr[tx + 16 * j];
#pragma unroll
                for (int i = 0; i < 4; i++) acc[i][j] += p[i] * vv;
            }
        }
        __syncthreads();
    }

    // epilogue: write valid rows only (pad rows handled by fill kernel)
    int lenb = lenp[b];
#pragma unroll
    for (int i = 0; i < 4; i++) {
        int t = r0 + 4 * ty + i;
        if (t < lenb) {
            float inv = 1.f / l_i[i];
            float* orow = out + ((size_t)(b * TT + t)) * DD;
#pragma unroll
            for (int j = 0; j < 16; j++)
                orow[tx + 16 * j] = acc[i][j] * inv;
        }
    }
}

// ---------------- pad rows: uniform softmax over all T -> mean(v) -----------
__global__ void fill_kernel(const int* __restrict__ lenp, float* __restrict__ out)
{
    int b = blockIdx.y, t = blockIdx.x, d = threadIdx.x;
    if (t >= lenp[b])
        out[((size_t)(b * TT + t)) * DD + d] = g_vmean[b * DD + d];
}

// ---------------- launcher ---------------------------------------------------
extern "C" void kernel_launch(void* const* d_in, const int* in_sizes, int n_in,
                              void* d_out, int out_size)
{
    (void)in_sizes; (void)n_in; (void)out_size;

    const float* query = (const float*)d_in[0];
    const float* value = (const float*)d_in[1];
    const float* aux   = (const float*)d_in[2];
    const int*   lenp  = (const int*)d_in[3];
    const float* Wql = (const float*)d_in[4];
    const float* bql = (const float*)d_in[5];
    const float* Wq  = (const float*)d_in[6];
    const float* bq  = (const float*)d_in[7];
    const float* aq  = (const float*)d_in[8];
    const float* gq  = (const float*)d_in[9];
    const float* btq = (const float*)d_in[10];
    const float* Wk  = (const float*)d_in[11];
    const float* bk  = (const float*)d_in[12];
    const float* ak  = (const float*)d_in[13];
    const float* gk  = (const float*)d_in[14];
    const float* btk = (const float*)d_in[15];
    const float* Wv  = (const float*)d_in[16];
    const float* bv  = (const float*)d_in[17];
    const float* av  = (const float*)d_in[18];
    const float* gv  = (const float*)d_in[19];
    const float* btv = (const float*)d_in[20];
    const float* Ws  = (const float*)d_in[21];
    const float* bs  = (const float*)d_in[22];
    const float* Wt  = (const float*)d_in[23];
    const float* bt  = (const float*)d_in[24];
    float* out = (float*)d_out;

    float *pq, *pk, *pv1, *pv, *pweff, *pbq, *pbk, *pbv;
    cudaGetSymbolAddress((void**)&pq, g_q);
    cudaGetSymbolAddress((void**)&pk, g_k);
    cudaGetSymbolAddress((void**)&pv1, g_v1);
    cudaGetSymbolAddress((void**)&pv, g_v);
    cudaGetSymbolAddress((void**)&pweff, g_weff);
    cudaGetSymbolAddress((void**)&pbq, g_bq);
    cudaGetSymbolAddress((void**)&pbk, g_bk);
    cudaGetSymbolAddress((void**)&pbv, g_bv);

    // 1. fold q-path weights: Weff = Wql @ Wq[0:256,:]
    matmul256_kernel<<<dim3(16, 16), dim3(16, 16)>>>(Wql, Wq, pweff);

    // 2. per-batch effective biases (aux term + bias folds)
    bias_kernel<<<BB, DD>>>(aux, Wq + DD * DD, bq, bql, Wq, 1, pbq);
    bias_kernel<<<BB, DD>>>(aux, Wk + DD * DD, bk, nullptr, nullptr, 0, pbk);
    bias_kernel<<<BB, DD>>>(aux, Wv + DD * DD, bv, nullptr, nullptr, 0, pbv);

    // 3. fused GEMM + PReLU + LN for q, k, v
    gemm_ln_kernel<<<BT / GROWS, 256>>>(query, pweff, pbq, aq, gq, btq, pq);
    gemm_ln_kernel<<<BT / GROWS, 256>>>(value, Wk, pbk, ak, gk, btk, pk);
    gemm_ln_kernel<<<BT / GROWS, 256>>>(value, Wv, pbv, av, gv, btv, pv1);

    // 4. gate
    gate_kernel<<<BT / GROWS, 256>>>(pv1, Ws, Wt, bs, bt, pv);

    // 5. column means of gated v (for pad rows)
    vpart_kernel<<<dim3(BB, 16), DD>>>();
    vmean_kernel<<<BB, DD>>>();

    // 6. causal flash attention over valid rows
    size_t smem = (size_t)(FBM * QSTR + FBN * QSTR + FBN * DD + FBM * PSTR) * sizeof(float);
    cudaFuncSetAttribute(flash_kernel, cudaFuncAttributeMaxDynamicSharedMemorySize, (int)smem);
    flash_kernel<<<dim3(TT / FBM, BB), 256, smem>>>(lenp, out);

    // 7. pad rows
    fill_kernel<<<dim3(TT, BB), DD>>>(lenp, out);
}

// round 3
// speedup vs baseline: 1.0505x; 1.0505x over previous
#include <cuda_runtime.h>
#include <math.h>

#define BB 8
#define TT 2048
#define DD 256
#define BT (BB*TT)

// ---------------- scratch (static device arrays; no cudaMalloc allowed) ----
__device__ float g_q[BT*DD];
__device__ float g_k[BT*DD];
__device__ float g_v1[BT*DD];   // LN'd v before gate
__device__ float g_v[BT*DD];    // gated v
__device__ float g_weff[DD*DD];
__device__ float g_bq[BB*DD];
__device__ float g_bk[BB*DD];
__device__ float g_bv[BB*DD];
__device__ float g_vpart[BB*16*DD];
__device__ float g_vmean[BB*DD];

// ---------------- small 256x256x256 matmul: C = A @ B -----------------------
__global__ void matmul256_kernel(const float* __restrict__ A,
                                 const float* __restrict__ Bm,
                                 float* __restrict__ C)
{
    __shared__ float As[16][16];
    __shared__ float Bs[16][17];
    int tx = threadIdx.x, ty = threadIdx.y;
    int row = blockIdx.y * 16 + ty;
    int col = blockIdx.x * 16 + tx;
    float acc = 0.f;
    for (int k0 = 0; k0 < DD; k0 += 16) {
        As[ty][tx] = A[row * DD + k0 + tx];
        Bs[ty][tx] = Bm[(k0 + ty) * DD + col];
        __syncthreads();
#pragma unroll
        for (int k = 0; k < 16; k++) acc += As[ty][k] * Bs[k][tx];
        __syncthreads();
    }
    C[row * DD + col] = acc;
}

// ---------------- per-batch effective bias ---------------------------------
// out[b][n] = bblk[n] + sum_d aux[b][d]*WB[d][n] (+ sum_d bin[d]*WA[d][n] if fold)
__global__ void bias_kernel(const float* __restrict__ aux,
                            const float* __restrict__ WB,
                            const float* __restrict__ bblk,
                            const float* __restrict__ bin,
                            const float* __restrict__ WA,
                            int fold,
                            float* __restrict__ outBD)
{
    int b = blockIdx.x, n = threadIdx.x;
    float acc = bblk[n];
    for (int d = 0; d < DD; d++) acc += aux[b * DD + d] * WB[d * DD + n];
    if (fold) {
        for (int d = 0; d < DD; d++) acc += bin[d] * WA[d * DD + n];
    }
    outBD[b * DD + n] = acc;
}

// ---------------- fused GEMM (16384x256 @ 256x256) + bias + PReLU + LN -----
#define GROWS 32
#define KC 32
__global__ __launch_bounds__(256) void gemm_ln_kernel(
    const float* __restrict__ X, const float* __restrict__ W,
    const float* __restrict__ biasBD, const float* __restrict__ aP,
    const float* __restrict__ gam, const float* __restrict__ beta,
    float* __restrict__ out)
{
    __shared__ float Xs[GROWS][KC];   // 4KB
    __shared__ float Ws[KC][DD];      // 32KB
    int tid = threadIdx.x;
    int ty = tid >> 5, tx = tid & 31;  // warp = 4 rows
    int row0 = blockIdx.x * GROWS;

    float acc[4][8];
#pragma unroll
    for (int i = 0; i < 4; i++)
#pragma unroll
        for (int j = 0; j < 8; j++) acc[i][j] = 0.f;

    for (int k0 = 0; k0 < DD; k0 += KC) {
        // load X tile: 32x32 floats = 256 float4, one per thread
        {
            int r = tid >> 3, c4 = tid & 7;
            ((float4*)&Xs[r][0])[c4] =
                ((const float4*)(X + (size_t)(row0 + r) * DD + k0))[c4];
        }
        // load W tile: 32x256 = 2048 float4, 8 per thread
#pragma unroll
        for (int it = 0; it < 8; it++) {
            int i = tid + it * 256;
            int r = i >> 6, c4 = i & 63;
            ((float4*)&Ws[r][0])[c4] =
                ((const float4*)(W + (size_t)(k0 + r) * DD))[c4];
        }
        __syncthreads();
#pragma unroll
        for (int kk = 0; kk < KC; kk++) {
            float xv[4], wv[8];
#pragma unroll
            for (int i = 0; i < 4; i++) xv[i] = Xs[4 * ty + i][kk];
#pragma unroll
            for (int j = 0; j < 8; j++) wv[j] = Ws[kk][tx + 32 * j];
#pragma unroll
            for (int i = 0; i < 4; i++)
#pragma unroll
                for (int j = 0; j < 8; j++) acc[i][j] += xv[i] * wv[j];
        }
        __syncthreads();
    }

    // epilogue: bias + PReLU + LayerNorm per row (warp owns 4 full rows)
    int b = row0 / TT;
    float a = aP[0];
    float gv[8], bv2[8], bias[8];
#pragma unroll
    for (int j = 0; j < 8; j++) {
        int col = tx + 32 * j;
        bias[j] = biasBD[b * DD + col];
        gv[j] = gam[col];
        bv2[j] = beta[col];
    }
#pragma unroll
    for (int i = 0; i < 4; i++) {
        float v[8];
        float sum = 0.f;
#pragma unroll
        for (int j = 0; j < 8; j++) {
            float t = acc[i][j] + bias[j];
            t = (t >= 0.f) ? t : a * t;   // PReLU
            v[j] = t;
            sum += t;
        }
#pragma unroll
        for (int o = 16; o > 0; o >>= 1) sum += __shfl_xor_sync(0xffffffffu, sum, o);
        float mean = sum * (1.f / DD);
        float sq = 0.f;
#pragma unroll
        for (int j = 0; j < 8; j++) { float d = v[j] - mean; sq += d * d; }
#pragma unroll
        for (int o = 16; o > 0; o >>= 1) sq += __shfl_xor_sync(0xffffffffu, sq, o);
        float rstd = rsqrtf(sq * (1.f / DD) + 1e-5f);
        int row = row0 + 4 * ty + i;
        float* orow = out + (size_t)row * DD;
#pragma unroll
        for (int j = 0; j < 8; j++)
            orow[tx + 32 * j] = (v[j] - mean) * rstd * gv[j] + bv2[j];
    }
}

// ---------------- gate: v = sigmoid(x@Ws+bs) * tanh(x@Wt+bt) ---------------
#define KCG 16
__global__ __launch_bounds__(256) void gate_kernel(
    const float* __restrict__ X, const float* __restrict__ Wsm,
    const float* __restrict__ Wtm, const float* __restrict__ bs,
    const float* __restrict__ bt, float* __restrict__ out)
{
    __shared__ float Xs[GROWS][KCG];   // 2KB
    __shared__ float Wss[KCG][DD];     // 16KB
    __shared__ float Wts[KCG][DD];     // 16KB
    int tid = threadIdx.x;
    int ty = tid >> 5, tx = tid & 31;
    int row0 = blockIdx.x * GROWS;

    float accs[4][8], acct[4][8];
#pragma unroll
    for (int i = 0; i < 4; i++)
#pragma unroll
        for (int j = 0; j < 8; j++) { accs[i][j] = 0.f; acct[i][j] = 0.f; }

    for (int k0 = 0; k0 < DD; k0 += KCG) {
        // X tile: 32x16 = 128 float4
        if (tid < 128) {
            int r = tid >> 2, c4 = tid & 3;
            ((float4*)&Xs[r][0])[c4] =
                ((const float4*)(X + (size_t)(row0 + r) * DD + k0))[c4];
        }
        // W tiles: 16x256 = 1024 float4 each, 4 per thread each
#pragma unroll
        for (int it = 0; it < 4; it++) {
            int i = tid + it * 256;
            int r = i >> 6, c4 = i & 63;
            ((float4*)&Wss[r][0])[c4] =
                ((const float4*)(Wsm + (size_t)(k0 + r) * DD))[c4];
            ((float4*)&Wts[r][0])[c4] =
                ((const float4*)(Wtm + (size_t)(k0 + r) * DD))[c4];
        }
        __syncthreads();
#pragma unroll
        for (int kk = 0; kk < KCG; kk++) {
            float xv[4], ws[8], wt[8];
#pragma unroll
            for (int i = 0; i < 4; i++) xv[i] = Xs[4 * ty + i][kk];
#pragma unroll
            for (int j = 0; j < 8; j++) {
                ws[j] = Wss[kk][tx + 32 * j];
                wt[j] = Wts[kk][tx + 32 * j];
            }
#pragma unroll
            for (int i = 0; i < 4; i++)
#pragma unroll
                for (int j = 0; j < 8; j++) {
                    accs[i][j] += xv[i] * ws[j];
                    acct[i][j] += xv[i] * wt[j];
                }
        }
        __syncthreads();
    }

#pragma unroll
    for (int i = 0; i < 4; i++) {
        int row = row0 + 4 * ty + i;
        float* orow = out + (size_t)row * DD;
#pragma unroll
        for (int j = 0; j < 8; j++) {
            int col = tx + 32 * j;
            float s = accs[i][j] + bs[col];
            float t = acct[i][j] + bt[col];
            float sig = 1.f / (1.f + __expf(-s));
            orow[col] = sig * tanhf(t);
        }
    }
}

// ---------------- v column means (for pad rows) -----------------------------
__global__ void vpart_kernel()
{
    int b = blockIdx.x, c = blockIdx.y, d = threadIdx.x;
    float s = 0.f;
    const float* base = g_v + ((size_t)(b * TT + c * 128)) * DD + d;
    for (int i = 0; i < 128; i++) s += base[(size_t)i * DD];
    g_vpart[(b * 16 + c) * DD + d] = s;
}

__global__ void vmean_kernel()
{
    int b = blockIdx.x, d = threadIdx.x;
    float s = 0.f;
    for (int c = 0; c < 16; c++) s += g_vpart[(b * 16 + c) * DD + d];
    g_vmean[b * DD + d] = s * (1.f / TT);
}

// ---------------- flash attention (fp32, causal, valid rows) ----------------
#define FBM 64
#define FBN 64
#define QSTR 257
#define PSTR 68

__global__ __launch_bounds__(256, 1) void flash_kernel(
    const int* __restrict__ lenp, float* __restrict__ out)
{
    extern __shared__ float sm[];
    float* Qs = sm;                        // 64 x 257
    float* Ks = Qs + FBM * QSTR;           // 64 x 257
    float* Vs = Ks + FBN * QSTR;           // 64 x 256
    float* Ps = Vs + FBN * DD;             // 64 x 68

    int b = blockIdx.y;
    int qt = gridDim.x - 1 - blockIdx.x;   // big tiles launch first
    int tid = threadIdx.x;
    int ty = tid >> 4, tx = tid & 15;
    int r0 = qt * FBM;

    const float SCALE = 1.f / 16.f;        // 1/sqrt(256)

    // load Q tile (pre-scaled)
    {
        const float* qbase = g_q + ((size_t)(b * TT + r0)) * DD;
#pragma unroll
        for (int it = 0; it < 16; it++) {
            int i = tid + it * 256;        // 4096 float4 total
            int r = i >> 6, c4 = i & 63;
            float4 v = ((const float4*)(qbase + (size_t)r * DD))[c4];
            float* dst = Qs + r * QSTR + c4 * 4;
            dst[0] = v.x * SCALE; dst[1] = v.y * SCALE;
            dst[2] = v.z * SCALE; dst[3] = v.w * SCALE;
        }
    }

    float m_i[4], l_i[4], acc[4][16];
#pragma unroll
    for (int i = 0; i < 4; i++) {
        m_i[i] = -1e30f; l_i[i] = 0.f;
#pragma unroll
        for (int j = 0; j < 16; j++) acc[i][j] = 0.f;
    }
    __syncthreads();

    for (int st = 0; st <= qt; ++st) {
        int s0 = st * FBN;
        // load K, V tiles
        {
            const float* kbase = g_k + ((size_t)(b * TT + s0)) * DD;
            const float* vbase = g_v + ((size_t)(b * TT + s0)) * DD;
#pragma unroll
            for (int it = 0; it < 16; it++) {
                int i = tid + it * 256;
                int r = i >> 6, c4 = i & 63;
                float4 kv = ((const float4*)(kbase + (size_t)r * DD))[c4];
                float* kd = Ks + r * QSTR + c4 * 4;
                kd[0] = kv.x; kd[1] = kv.y; kd[2] = kv.z; kd[3] = kv.w;
                ((float4*)(Vs + r * DD))[c4] =
                    ((const float4*)(vbase + (size_t)r * DD))[c4];
            }
        }
        __syncthreads();

        // S = Q @ K^T : rows 4ty+i, cols tx+16j
        float sacc[4][4];
#pragma unroll
        for (int i = 0; i < 4; i++)
#pragma unroll
            for (int j = 0; j < 4; j++) sacc[i][j] = 0.f;

        const float* qrow0 = Qs + (4 * ty) * QSTR;
        const float* kcol0 = Ks + tx * QSTR;
#pragma unroll 4
        for (int k = 0; k < DD; k++) {
            float qv[4], kv[4];
#pragma unroll
            for (int i = 0; i < 4; i++) qv[i] = qrow0[i * QSTR + k];
#pragma unroll
            for (int j = 0; j < 4; j++) kv[j] = kcol0[j * 16 * QSTR + k];
#pragma unroll
            for (int i = 0; i < 4; i++)
#pragma unroll
                for (int j = 0; j < 4; j++) sacc[i][j] += qv[i] * kv[j];
        }

        // causal mask on diagonal tile
        if (st == qt) {
#pragma unroll
            for (int i = 0; i < 4; i++)
#pragma unroll
                for (int j = 0; j < 4; j++)
                    if (s0 + tx + 16 * j > r0 + 4 * ty + i) sacc[i][j] = -1e30f;
        }

        // online softmax
        float mnew[4], lad[4];
#pragma unroll
        for (int i = 0; i < 4; i++) {
            float mx = sacc[i][0];
#pragma unroll
            for (int j = 1; j < 4; j++) mx = fmaxf(mx, sacc[i][j]);
#pragma unroll
            for (int o = 1; o < 16; o <<= 1)
                mx = fmaxf(mx, __shfl_xor_sync(0xffffffffu, mx, o));
            mnew[i] = fmaxf(m_i[i], mx);
        }
#pragma unroll
        for (int i = 0; i < 4; i++) {
            float sum = 0.f;
            float* prow = Ps + (4 * ty + i) * PSTR;
#pragma unroll
            for (int j = 0; j < 4; j++) {
                float p = __expf(sacc[i][j] - mnew[i]);
                sum += p;
                prow[tx + 16 * j] = p;
            }
#pragma unroll
            for (int o = 1; o < 16; o <<= 1)
                sum += __shfl_xor_sync(0xffffffffu, sum, o);
            lad[i] = sum;
        }
#pragma unroll
        for (int i = 0; i < 4; i++) {
            float f = __expf(m_i[i] - mnew[i]);
            l_i[i] = l_i[i] * f + lad[i];
            m_i[i] = mnew[i];
#pragma unroll
            for (int j = 0; j < 16; j++) acc[i][j] *= f;
        }
        __syncthreads();

        // O += P @ V : rows 4ty+i, cols tx+16j
        const float* prow0 = Ps + (4 * ty) * PSTR;
#pragma unroll 2
        for (int kk = 0; kk < FBN; kk++) {
            float p[4];
#pragma unroll
            for (int i = 0; i < 4; i++) p[i] = prow0[i * PSTR + kk];
            const float* vr = Vs + kk * DD;
#pragma unroll
            for (int j = 0; j < 16; j++) {
                float vv = vr[tx + 16 * j];
#pragma unroll
                for (int i = 0; i < 4; i++) acc[i][j] += p[i] * vv;
            }
        }
        __syncthreads();
    }

    // epilogue: write valid rows only (pad rows handled by fill kernel)
    int lenb = lenp[b];
#pragma unroll
    for (int i = 0; i < 4; i++) {
        int t = r0 + 4 * ty + i;
        if (t < lenb) {
            float inv = 1.f / l_i[i];
            float* orow = out + ((size_t)(b * TT + t)) * DD;
#pragma unroll
            for (int j = 0; j < 16; j++)
                orow[tx + 16 * j] = acc[i][j] * inv;
        }
    }
}

// ---------------- pad rows: uniform softmax over all T -> mean(v) -----------
__global__ void fill_kernel(const int* __restrict__ lenp, float* __restrict__ out)
{
    int b = blockIdx.y, t = blockIdx.x, d = threadIdx.x;
    if (t >= lenp[b])
        out[((size_t)(b * TT + t)) * DD + d] = g_vmean[b * DD + d];
}

// ---------------- launcher ---------------------------------------------------
extern "C" void kernel_launch(void* const* d_in, const int* in_sizes, int n_in,
                              void* d_out, int out_size)
{
    (void)in_sizes; (void)n_in; (void)out_size;

    const float* query = (const float*)d_in[0];
    const float* value = (const float*)d_in[1];
    const float* aux   = (const float*)d_in[2];
    const int*   lenp  = (const int*)d_in[3];
    const float* Wql = (const float*)d_in[4];
    const float* bql = (const float*)d_in[5];
    const float* Wq  = (const float*)d_in[6];
    const float* bq  = (const float*)d_in[7];
    const float* aq  = (const float*)d_in[8];
    const float* gq  = (const float*)d_in[9];
    const float* btq = (const float*)d_in[10];
    const float* Wk  = (const float*)d_in[11];
    const float* bk  = (const float*)d_in[12];
    const float* ak  = (const float*)d_in[13];
    const float* gk  = (const float*)d_in[14];
    const float* btk = (const float*)d_in[15];
    const float* Wv  = (const float*)d_in[16];
    const float* bv  = (const float*)d_in[17];
    const float* av  = (const float*)d_in[18];
    const float* gv  = (const float*)d_in[19];
    const float* btv = (const float*)d_in[20];
    const float* Ws  = (const float*)d_in[21];
    const float* bs  = (const float*)d_in[22];
    const float* Wt  = (const float*)d_in[23];
    const float* bt  = (const float*)d_in[24];
    float* out = (float*)d_out;

    float *pq, *pk, *pv1, *pv, *pweff, *pbq, *pbk, *pbv;
    cudaGetSymbolAddress((void**)&pq, g_q);
    cudaGetSymbolAddress((void**)&pk, g_k);
    cudaGetSymbolAddress((void**)&pv1, g_v1);
    cudaGetSymbolAddress((void**)&pv, g_v);
    cudaGetSymbolAddress((void**)&pweff, g_weff);
    cudaGetSymbolAddress((void**)&pbq, g_bq);
    cudaGetSymbolAddress((void**)&pbk, g_bk);
    cudaGetSymbolAddress((void**)&pbv, g_bv);

    // 1. fold q-path weights: Weff = Wql @ Wq[0:256,:]
    matmul256_kernel<<<dim3(16, 16), dim3(16, 16)>>>(Wql, Wq, pweff);

    // 2. per-batch effective biases (aux term + bias folds)
    bias_kernel<<<BB, DD>>>(aux, Wq + DD * DD, bq, bql, Wq, 1, pbq);
    bias_kernel<<<BB, DD>>>(aux, Wk + DD * DD, bk, nullptr, nullptr, 0, pbk);
    bias_kernel<<<BB, DD>>>(aux, Wv + DD * DD, bv, nullptr, nullptr, 0, pbv);

    // 3. fused GEMM + PReLU + LN for q, k, v
    gemm_ln_kernel<<<BT / GROWS, 256>>>(query, pweff, pbq, aq, gq, btq, pq);
    gemm_ln_kernel<<<BT / GROWS, 256>>>(value, Wk, pbk, ak, gk, btk, pk);
    gemm_ln_kernel<<<BT / GROWS, 256>>>(value, Wv, pbv, av, gv, btv, pv1);

    // 4. gate
    gate_kernel<<<BT / GROWS, 256>>>(pv1, Ws, Wt, bs, bt, pv);

    // 5. column means of gated v (for pad rows)
    vpart_kernel<<<dim3(BB, 16), DD>>>();
    vmean_kernel<<<BB, DD>>>();

    // 6. causal flash attention over valid rows
    size_t smem = (size_t)(FBM * QSTR + FBN * QSTR + FBN * DD + FBM * PSTR) * sizeof(float);
    cudaFuncSetAttribute(flash_kernel, cudaFuncAttributeMaxDynamicSharedMemorySize, (int)smem);
    flash_kernel<<<dim3(TT / FBM, BB), 256, smem>>>(lenp, out);

    // 7. pad rows
    fill_kernel<<<dim3(TT, BB), DD>>>(lenp, out);
}